// round 10
// baseline (speedup 1.0000x reference)
#include <cuda_runtime.h>
#include <cuda_bf16.h>
#include <cstdint>

// Problem constants
#define B_  4
#define S_  8192
#define D_  1024
#define H_  16
#define DK_ 64
#define EPSF 1e-6f
#define MROWS (B_ * S_)

// ---------------------------------------------------------------------------
// Scratch (device globals — no runtime allocation allowed)
// ---------------------------------------------------------------------------
__device__ float g_Q[(size_t)B_ * S_ * D_];
__device__ float g_K[(size_t)B_ * S_ * D_];
__device__ float g_V[(size_t)B_ * S_ * D_];
__device__ float g_kv[(size_t)B_ * H_ * DK_ * DK_];
__device__ float g_ktot[B_ * H_];
__device__ __nv_bfloat16 g_Wh[4ull * 1024 * 1024];
__device__ __nv_bfloat16 g_Wl[4ull * 1024 * 1024];
__device__ __nv_bfloat16 g_Ph[(size_t)MROWS * 1024];
__device__ __nv_bfloat16 g_Pl[(size_t)MROWS * 1024];

// ---------------------------------------------------------------------------
// PTX helpers (sm_80-level PTX only — ptxas target is sm_103 non-'a')
// ---------------------------------------------------------------------------
__device__ __forceinline__ uint32_t smem_u32(const void* p) {
    uint32_t a;
    asm("{ .reg .u64 t; cvta.to.shared.u64 t, %1; cvt.u32.u64 %0, t; }"
        : "=r"(a) : "l"(p));
    return a;
}
__device__ __forceinline__ void ldsm_x4(uint32_t& r0, uint32_t& r1,
                                        uint32_t& r2, uint32_t& r3, uint32_t addr) {
    asm volatile("ldmatrix.sync.aligned.m8n8.x4.shared.b16 {%0,%1,%2,%3}, [%4];"
                 : "=r"(r0), "=r"(r1), "=r"(r2), "=r"(r3) : "r"(addr));
}
__device__ __forceinline__ void mma_bf16(float* c, const uint32_t* a, const uint32_t* b) {
    asm volatile(
        "mma.sync.aligned.m16n8k16.row.col.f32.bf16.bf16.f32 "
        "{%0,%1,%2,%3}, {%4,%5,%6,%7}, {%8,%9}, {%0,%1,%2,%3};"
        : "+f"(c[0]), "+f"(c[1]), "+f"(c[2]), "+f"(c[3])
        : "r"(a[0]), "r"(a[1]), "r"(a[2]), "r"(a[3]), "r"(b[0]), "r"(b[1]));
}
__device__ __forceinline__ void cpa16(uint32_t dst, const void* src) {
    asm volatile("cp.async.ca.shared.global [%0], [%1], 16;" :: "r"(dst), "l"(src));
}
__device__ __forceinline__ void cpa_commit() {
    asm volatile("cp.async.commit_group;" ::: "memory");
}
__device__ __forceinline__ void cpa_wait1() {
    asm volatile("cp.async.wait_group 1;" ::: "memory");
}
__device__ __forceinline__ void sts64(uint32_t addr, uint32_t a, uint32_t b) {
    asm volatile("st.shared.v2.b32 [%0], {%1, %2};"
                 :: "r"(addr), "r"(a), "r"(b) : "memory");
}
// Pack 2 floats -> bf16x2 (x in low half, y in high half), and hi/lo split.
__device__ __forceinline__ uint32_t cvt_bf16x2(float hi_y, float lo_x) {
    uint32_t r;
    asm("cvt.rn.bf16x2.f32 %0, %1, %2;" : "=r"(r) : "f"(hi_y), "f"(lo_x));
    return r;
}
__device__ __forceinline__ void split2(float x, float y, uint32_t& h2, uint32_t& l2) {
    h2 = cvt_bf16x2(y, x);
    float fx = __uint_as_float(h2 << 16);
    float fy = __uint_as_float(h2 & 0xFFFF0000u);
    l2 = cvt_bf16x2(y - fy, x - fx);
}

// ---------------------------------------------------------------------------
// Weight pre-split: two fp32 matrices -> bf16 hi/lo each (one launch for two)
// ---------------------------------------------------------------------------
__global__ __launch_bounds__(256) void split_w2(
    const float* __restrict__ W0, __nv_bfloat16* __restrict__ Wh0,
    __nv_bfloat16* __restrict__ Wl0,
    const float* __restrict__ W1, __nv_bfloat16* __restrict__ Wh1,
    __nv_bfloat16* __restrict__ Wl1)
{
    int half = blockIdx.x >> 10;
    int i = ((blockIdx.x & 1023) * 256 + threadIdx.x) * 4;
    const float* W = half ? W1 : W0;
    __nv_bfloat16* Wh = half ? Wh1 : Wh0;
    __nv_bfloat16* Wl = half ? Wl1 : Wl0;
    float4 v = *reinterpret_cast<const float4*>(W + i);
    uint32_t h0, l0, h1, l1;
    split2(v.x, v.y, h0, l0);
    split2(v.z, v.w, h1, l1);
    uint32_t* whp = reinterpret_cast<uint32_t*>(Wh + i);
    uint32_t* wlp = reinterpret_cast<uint32_t*>(Wl + i);
    whp[0] = h0; whp[1] = h1;
    wlp[0] = l0; wlp[1] = l1;
}

// ---------------------------------------------------------------------------
// HMMA GEMM: C[M,1024] = A[M,1024] @ W[1024,1024]^T   (unchanged from R9)
// ---------------------------------------------------------------------------
#define SUBT    8192
#define A_RING  (2 * 2 * SUBT)
#define W_BASE  A_RING
#define SMEMSZ  (A_RING + 3 * 2 * SUBT)   // 81920

template <int APRE>
__global__ __launch_bounds__(256, 2) void gemm_tc(
    const float* __restrict__ A32,
    const __nv_bfloat16* __restrict__ Ahp,
    const __nv_bfloat16* __restrict__ Alp,
    const __nv_bfloat16* __restrict__ Wh,
    const __nv_bfloat16* __restrict__ Wl,
    float* __restrict__ C, int act)
{
    extern __shared__ __align__(128) char smc[];
    const uint32_t sb0 = smem_u32(smc);
    const int tid = threadIdx.x;
    const int lane = tid & 31, w = tid >> 5;
    const int wm = w >> 2, wn = w & 3;
    const int bx = blockIdx.x, by = blockIdx.y;

    const float* Ab = A32 + (size_t)by * 128 * 1024;
    const __nv_bfloat16* AhB = Ahp + (size_t)by * 128 * 1024;
    const __nv_bfloat16* AlB = Alp + (size_t)by * 128 * 1024;
    const __nv_bfloat16* WhB = Wh + (size_t)bx * 128 * 1024;
    const __nv_bfloat16* WlB = Wl + (size_t)bx * 128 * 1024;

    float acc[4][4][4];
#pragma unroll
    for (int i = 0; i < 4; i++)
#pragma unroll
        for (int j = 0; j < 4; j++)
#pragma unroll
            for (int q = 0; q < 4; q++) acc[i][j][q] = 0.f;

    uint32_t fa[4][4], fbH[4][2], fbL[4][2];
    float4 areg[4];

    auto Ast = [&](int c) { return sb0 + (uint32_t)(c & 1) * (2 * SUBT); };
    auto Wst = [&](int c) { return sb0 + W_BASE + (uint32_t)(c % 3) * (2 * SUBT); };

    const int aRowBase = wm * 64 + (lane & 15);
    const int aHalf    = lane >> 4;
    const int swA      = (aRowBase >> 1) & 3;
    const uint32_t aByte = (uint32_t)aRowBase * 64;

    const int bRowBase = wn * 32 + ((lane >> 4) << 3) + (lane & 7);
    const int bHalf    = (lane >> 3) & 1;
    const int swB      = (bRowBase >> 1) & 3;
    const uint32_t bByte = (uint32_t)bRowBase * 64;

    auto LdgA = [&](int k0) {
#pragma unroll
        for (int i = 0; i < 4; i++) {
            int idx = tid + i * 256;
            int r = idx >> 3, c4 = idx & 7;
            areg[i] = *reinterpret_cast<const float4*>(
                Ab + (size_t)r * 1024 + k0 + c4 * 4);
        }
    };
    auto StsA = [&](uint32_t sb) {
#pragma unroll
        for (int i = 0; i < 4; i++) {
            int idx = tid + i * 256;
            int r = idx >> 3, c4 = idx & 7;
            int ch = c4 >> 1, sub = c4 & 1;
            uint32_t off = (uint32_t)(r * 64 + ((ch ^ ((r >> 1) & 3)) << 4) + sub * 8);
            float4 v = areg[i];
            uint32_t h0, l0, h1, l1;
            split2(v.x, v.y, h0, l0);
            split2(v.z, v.w, h1, l1);
            sts64(sb + off, h0, h1);
            sts64(sb + SUBT + off, l0, l1);
        }
    };
    auto CpA = [&](uint32_t sb, int k0) {
#pragma unroll
        for (int i = 0; i < 2; i++) {
            int idx = tid + i * 256;
            int r = idx >> 2, ch = idx & 3;
            uint32_t dst = (uint32_t)(r * 64 + ((ch ^ ((r >> 1) & 3)) << 4));
            size_t src = (size_t)r * 1024 + k0 + ch * 8;
            cpa16(sb + dst, AhB + src);
            cpa16(sb + SUBT + dst, AlB + src);
        }
    };
    auto CpW = [&](uint32_t sb, int k0) {
#pragma unroll
        for (int i = 0; i < 2; i++) {
            int idx = tid + i * 256;
            int r = idx >> 2, ch = idx & 3;
            uint32_t dst = (uint32_t)(r * 64 + ((ch ^ ((r >> 1) & 3)) << 4));
            size_t src = (size_t)r * 1024 + k0 + ch * 8;
            cpa16(sb + dst, WhB + src);
            cpa16(sb + SUBT + dst, WlB + src);
        }
    };

    auto LdA = [&](uint32_t base) {
#pragma unroll
        for (int mt = 0; mt < 4; mt++)
            ldsm_x4(fa[mt][0], fa[mt][1], fa[mt][2], fa[mt][3],
                    base + (uint32_t)mt * 1024);
    };
    auto LdB = [&](uint32_t b[4][2], uint32_t base) {
        ldsm_x4(b[0][0], b[0][1], b[1][0], b[1][1], base);
        ldsm_x4(b[2][0], b[2][1], b[3][0], b[3][1], base + 1024);
    };
    auto MmaAll = [&](uint32_t b[4][2]) {
#pragma unroll
        for (int mt = 0; mt < 4; mt++)
#pragma unroll
            for (int nf = 0; nf < 4; nf++)
                mma_bf16(acc[mt][nf], fa[mt], b[nf]);
    };

    if (APRE) {
        CpA(Ast(0), 0);
        CpW(Wst(0), 0);
        cpa_commit();
        CpW(Wst(1), 32);
        cpa_commit();
    } else {
        LdgA(0);
        StsA(Ast(0));
        CpW(Wst(0), 0);
        cpa_commit();
        CpW(Wst(1), 32);
        cpa_commit();
        LdgA(32);
    }

    for (int c = 0; c < 32; c++) {
        const uint32_t sa = Ast(c);
        const uint32_t sw = Wst(c);
        cpa_wait1();
        __syncthreads();

#pragma unroll
        for (int ks = 0; ks < 2; ks++) {
            const uint32_t ca = (uint32_t)(((2 * ks + aHalf) ^ swA) << 4);
            const uint32_t cb = (uint32_t)(((2 * ks + bHalf) ^ swB) << 4);
            LdA(sa + aByte + ca);
            LdB(fbH, sw + bByte + cb);
            MmaAll(fbH);
            LdB(fbL, sw + SUBT + bByte + cb);
            MmaAll(fbL);
            LdA(sa + SUBT + aByte + ca);
            MmaAll(fbH);
        }

        if (APRE) {
            if (c + 1 < 32) CpA(Ast(c + 1), (c + 1) * 32);
            cpa_commit();
            if (c + 2 < 32) CpW(Wst(c + 2), (c + 2) * 32);
            cpa_commit();
        } else {
            if (c + 1 < 32) StsA(Ast(c + 1));
            if (c + 2 < 32) CpW(Wst(c + 2), (c + 2) * 32);
            cpa_commit();
            cpa_commit();
            if (c + 2 < 32) LdgA((c + 2) * 32);
        }
    }

    const int mBase = by * 128 + wm * 64 + (lane >> 2);
    const int nBase = bx * 128 + wn * 32 + (lane & 3) * 2;
#pragma unroll
    for (int mt = 0; mt < 4; mt++) {
#pragma unroll
        for (int nf = 0; nf < 4; nf++) {
            int m = mBase + mt * 16;
            int n = nBase + nf * 8;
            float2 v0 = make_float2(acc[mt][nf][0], acc[mt][nf][1]);
            float2 v1 = make_float2(acc[mt][nf][2], acc[mt][nf][3]);
            if (act) {
                v0.x = fmaxf(v0.x, 0.f) + EPSF; v0.y = fmaxf(v0.y, 0.f) + EPSF;
                v1.x = fmaxf(v1.x, 0.f) + EPSF; v1.y = fmaxf(v1.y, 0.f) + EPSF;
            }
            *reinterpret_cast<float2*>(C + (size_t)m * 1024 + n) = v0;
            *reinterpret_cast<float2*>(C + (size_t)(m + 8) * 1024 + n) = v1;
        }
    }
}

// ---------------------------------------------------------------------------
// Zero kv / ktot
// ---------------------------------------------------------------------------
__global__ void zero_kv()
{
    int i = blockIdx.x * blockDim.x + threadIdx.x;
    if (i < B_ * H_ * DK_ * DK_) g_kv[i] = 0.f;
    if (i < B_ * H_) g_ktot[i] = 0.f;
}

// ---------------------------------------------------------------------------
// kv_reduce v2: 8x8 register tiles, float4 staging, 4-way s-split + smem merge
// kv[b,h,d,e] = sum_s K[b,s,h,d] * V[b,s,h,e] ; ktot[b,h] = sum K
// grid (B*H, S/SCHUNK), 256 threads
// ---------------------------------------------------------------------------
#define SCHUNK 512
#define KSTG   32

__global__ __launch_bounds__(256) void kv_reduce(
    const float* __restrict__ Kb, const float* __restrict__ Vb)
{
    __shared__ float sK[KSTG][DK_];
    __shared__ float sV[KSTG][DK_];
    __shared__ float sred[DK_ * DK_];

    const int bh = blockIdx.x;
    const int b = bh >> 4, h = bh & 15;
    const int s0 = blockIdx.y * SCHUNK;
    const int tid = threadIdx.x;
    const int g  = tid >> 6;            // 0..3 (s-split group)
    const int t6 = tid & 63;
    const int d0 = (t6 >> 3) << 3;      // 0..56
    const int e0 = (t6 & 7) << 3;       // 0..56

    float acc[8][8];
#pragma unroll
    for (int i = 0; i < 8; i++)
#pragma unroll
        for (int j = 0; j < 8; j++) acc[i][j] = 0.f;

    float ksum = 0.f;
    const size_t base = ((size_t)b * S_ + s0) * D_ + h * DK_;

    for (int so = 0; so < SCHUNK; so += KSTG) {
#pragma unroll
        for (int i = 0; i < 2; i++) {
            int f = tid + i * 256;             // 0..511 float4 slots
            int r = f >> 4, c4 = (f & 15) << 2;
            size_t off = base + (size_t)(so + r) * D_ + c4;
            float4 k4 = *reinterpret_cast<const float4*>(Kb + off);
            float4 v4 = *reinterpret_cast<const float4*>(Vb + off);
            ksum += k4.x + k4.y + k4.z + k4.w;
            *reinterpret_cast<float4*>(&sK[r][c4]) = k4;
            *reinterpret_cast<float4*>(&sV[r][c4]) = v4;
        }
        __syncthreads();
#pragma unroll
        for (int sr = 0; sr < 8; sr++) {
            int s = g * 8 + sr;
            float kd[8], ve[8];
            *reinterpret_cast<float4*>(&kd[0]) =
                *reinterpret_cast<float4*>(&sK[s][d0]);
            *reinterpret_cast<float4*>(&kd[4]) =
                *reinterpret_cast<float4*>(&sK[s][d0 + 4]);
            *reinterpret_cast<float4*>(&ve[0]) =
                *reinterpret_cast<float4*>(&sV[s][e0]);
            *reinterpret_cast<float4*>(&ve[4]) =
                *reinterpret_cast<float4*>(&sV[s][e0 + 4]);
#pragma unroll
            for (int i = 0; i < 8; i++)
#pragma unroll
                for (int j = 0; j < 8; j++)
                    acc[i][j] = fmaf(kd[i], ve[j], acc[i][j]);
        }
        __syncthreads();
    }

    // merge the 4 s-split groups in shared memory
    if (g == 0) {
#pragma unroll
        for (int i = 0; i < 8; i++)
#pragma unroll
            for (int j = 0; j < 8; j++)
                sred[(d0 + i) * DK_ + e0 + j] = acc[i][j];
    }
    __syncthreads();
#pragma unroll
    for (int gg = 1; gg < 4; gg++) {
        if (g == gg) {
#pragma unroll
            for (int i = 0; i < 8; i++)
#pragma unroll
                for (int j = 0; j < 8; j++)
                    sred[(d0 + i) * DK_ + e0 + j] += acc[i][j];
        }
        __syncthreads();
    }

    // global accumulation across S-chunks
    float* kvp = g_kv + (size_t)bh * DK_ * DK_;
    for (int t = tid; t < DK_ * DK_; t += 256)
        atomicAdd(&kvp[t], sred[t]);

    // ktot
#pragma unroll
    for (int o = 16; o > 0; o >>= 1)
        ksum += __shfl_xor_sync(0xFFFFFFFFu, ksum, o);
    if ((tid & 31) == 0) atomicAdd(&g_ktot[bh], ksum);
}

// ---------------------------------------------------------------------------
// apply_kv v2: 256 rows per CTA, transposed Q staging, 8x8 register tiles,
// zero mainloop barriers. P = (Q @ kv) / (rowsum(Q)*ktot + eps) -> bf16 hi/lo
// grid (B*H, S/256), 256 threads, dynamic smem
// ---------------------------------------------------------------------------
#define QPAD 257
#define APPLY_SMEM ((DK_ * DK_ + DK_ * QPAD) * 4)   // 16384 + 65792 = 82176

__global__ __launch_bounds__(256, 2) void apply_kv(
    const float* __restrict__ Qb,
    __nv_bfloat16* __restrict__ Ph, __nv_bfloat16* __restrict__ Pl)
{
    extern __shared__ float sdyn[];
    float* skv = sdyn;                  // [64*64]
    float* sQt = sdyn + DK_ * DK_;      // [64][QPAD] transposed Q

    const int bh = blockIdx.x;
    const int b = bh >> 4, h = bh & 15;
    const int tid = threadIdx.x;
    const int ri = tid >> 3;            // 0..31 -> rows 8ri..8ri+7
    const int cj = tid & 7;             // cols 8cj..8cj+7

    // load kv tile
    for (int t = tid; t < DK_ * DK_ / 4; t += 256)
        *reinterpret_cast<float4*>(&skv[t * 4]) =
            *reinterpret_cast<const float4*>(&g_kv[(size_t)bh * DK_ * DK_ + t * 4]);

    const float ktv = g_ktot[bh];
    const int row0 = blockIdx.y * 256;
    const size_t gbase = ((size_t)b * S_ + row0) * D_ + h * DK_;

    // stage 256 Q rows transposed: sQt[d][row]
#pragma unroll
    for (int i = 0; i < 16; i++) {
        int f = tid + i * 256;              // 0..4095 float4 slots
        int r = f >> 4, c4 = (f & 15) << 2;
        float4 q4 = *reinterpret_cast<const float4*>(Qb + gbase + (size_t)r * D_ + c4);
        sQt[(c4 + 0) * QPAD + r] = q4.x;
        sQt[(c4 + 1) * QPAD + r] = q4.y;
        sQt[(c4 + 2) * QPAD + r] = q4.z;
        sQt[(c4 + 3) * QPAD + r] = q4.w;
    }
    __syncthreads();

    float acc[8][8];
    float qsum[8];
#pragma unroll
    for (int r = 0; r < 8; r++) {
        qsum[r] = 0.f;
#pragma unroll
        for (int c = 0; c < 8; c++) acc[r][c] = 0.f;
    }

#pragma unroll 4
    for (int d = 0; d < DK_; d++) {
        float qv[8], kvv[8];
#pragma unroll
        for (int r = 0; r < 8; r++) qv[r] = sQt[d * QPAD + ri * 8 + r];
        *reinterpret_cast<float4*>(&kvv[0]) =
            *reinterpret_cast<float4*>(&skv[d * DK_ + cj * 8]);
        *reinterpret_cast<float4*>(&kvv[4]) =
            *reinterpret_cast<float4*>(&skv[d * DK_ + cj * 8 + 4]);
#pragma unroll
        for (int r = 0; r < 8; r++) {
            qsum[r] += qv[r];
#pragma unroll
            for (int c = 0; c < 8; c++)
                acc[r][c] = fmaf(qv[r], kvv[c], acc[r][c]);
        }
    }

    // normalize + emit bf16 hi/lo
#pragma unroll
    for (int r = 0; r < 8; r++) {
        int row = ri * 8 + r;
        float nrm = 1.f / (qsum[r] * ktv + EPSF);
        size_t off = gbase + (size_t)row * D_ + cj * 8;
        uint32_t hv[4], lv[4];
#pragma unroll
        for (int c = 0; c < 4; c++)
            split2(acc[r][2 * c] * nrm, acc[r][2 * c + 1] * nrm, hv[c], lv[c]);
        *reinterpret_cast<float4*>(Ph + off) = make_float4(
            __uint_as_float(hv[0]), __uint_as_float(hv[1]),
            __uint_as_float(hv[2]), __uint_as_float(hv[3]));
        *reinterpret_cast<float4*>(Pl + off) = make_float4(
            __uint_as_float(lv[0]), __uint_as_float(lv[1]),
            __uint_as_float(lv[2]), __uint_as_float(lv[3]));
    }
}

// ---------------------------------------------------------------------------
// Launch
// ---------------------------------------------------------------------------
extern "C" void kernel_launch(void* const* d_in, const int* in_sizes, int n_in,
                              void* d_out, int out_size)
{
    const float* q  = (const float*)d_in[0];
    const float* k  = (const float*)d_in[1];
    const float* v  = (const float*)d_in[2];
    const float* Wq = (const float*)d_in[3];
    const float* Wk = (const float*)d_in[4];
    const float* Wv = (const float*)d_in[5];
    const float* Wo = (const float*)d_in[6];
    float* out = (float*)d_out;

    float *Qb, *Kb, *Vb;
    __nv_bfloat16 *whp, *wlp, *php, *plp;
    cudaGetSymbolAddress((void**)&Qb, g_Q);
    cudaGetSymbolAddress((void**)&Kb, g_K);
    cudaGetSymbolAddress((void**)&Vb, g_V);
    cudaGetSymbolAddress((void**)&whp, g_Wh);
    cudaGetSymbolAddress((void**)&wlp, g_Wl);
    cudaGetSymbolAddress((void**)&php, g_Ph);
    cudaGetSymbolAddress((void**)&plp, g_Pl);

    cudaFuncSetAttribute(gemm_tc<0>, cudaFuncAttributeMaxDynamicSharedMemorySize,
                         SMEMSZ);
    cudaFuncSetAttribute(gemm_tc<1>, cudaFuncAttributeMaxDynamicSharedMemorySize,
                         SMEMSZ);
    cudaFuncSetAttribute(apply_kv, cudaFuncAttributeMaxDynamicSharedMemorySize,
                         APPLY_SMEM);

    const size_t WS = 1024ull * 1024ull;
    dim3 gg(8, MROWS / 128);   // x = N tiles (fast), y = M tiles

    zero_kv<<<(B_ * H_ * DK_ * DK_ + 255) / 256, 256>>>();
    split_w2<<<2048, 256>>>(Wq, whp + 0 * WS, wlp + 0 * WS,
                            Wk, whp + 1 * WS, wlp + 1 * WS);
    split_w2<<<2048, 256>>>(Wv, whp + 2 * WS, wlp + 2 * WS,
                            Wo, whp + 3 * WS, wlp + 3 * WS);

    gemm_tc<0><<<gg, 256, SMEMSZ>>>(q, php, plp, whp + 0 * WS, wlp + 0 * WS, Qb, 1);
    gemm_tc<0><<<gg, 256, SMEMSZ>>>(k, php, plp, whp + 1 * WS, wlp + 1 * WS, Kb, 1);
    gemm_tc<0><<<gg, 256, SMEMSZ>>>(v, php, plp, whp + 2 * WS, wlp + 2 * WS, Vb, 0);

    kv_reduce<<<dim3(B_ * H_, S_ / SCHUNK), 256>>>(Kb, Vb);
    apply_kv<<<dim3(B_ * H_, S_ / 256), 256, APPLY_SMEM>>>(Qb, php, plp);

    gemm_tc<1><<<gg, 256, SMEMSZ>>>(nullptr, php, plp, whp + 3 * WS, wlp + 3 * WS,
                                    out, 0);
}

// round 11
// speedup vs baseline: 1.5387x; 1.5387x over previous
#include <cuda_runtime.h>
#include <cuda_bf16.h>
#include <cstdint>

// Problem constants
#define B_  4
#define S_  8192
#define D_  1024
#define H_  16
#define DK_ 64
#define EPSF 1e-6f
#define MROWS (B_ * S_)

// ---------------------------------------------------------------------------
// Scratch (device globals — no runtime allocation allowed)
// ---------------------------------------------------------------------------
__device__ float g_Q[(size_t)B_ * S_ * D_];
__device__ float g_K[(size_t)B_ * S_ * D_];
__device__ float g_V[(size_t)B_ * S_ * D_];
__device__ float g_kv[(size_t)B_ * H_ * DK_ * DK_];
__device__ float g_ktot[B_ * H_];
__device__ __nv_bfloat16 g_Wh[4ull * 1024 * 1024];
__device__ __nv_bfloat16 g_Wl[4ull * 1024 * 1024];
__device__ __nv_bfloat16 g_Ph[(size_t)MROWS * 1024];
__device__ __nv_bfloat16 g_Pl[(size_t)MROWS * 1024];

// ---------------------------------------------------------------------------
// PTX helpers (sm_80-level PTX only — ptxas target is sm_103 non-'a')
// ---------------------------------------------------------------------------
__device__ __forceinline__ uint32_t smem_u32(const void* p) {
    uint32_t a;
    asm("{ .reg .u64 t; cvta.to.shared.u64 t, %1; cvt.u32.u64 %0, t; }"
        : "=r"(a) : "l"(p));
    return a;
}
__device__ __forceinline__ void ldsm_x4(uint32_t& r0, uint32_t& r1,
                                        uint32_t& r2, uint32_t& r3, uint32_t addr) {
    asm volatile("ldmatrix.sync.aligned.m8n8.x4.shared.b16 {%0,%1,%2,%3}, [%4];"
                 : "=r"(r0), "=r"(r1), "=r"(r2), "=r"(r3) : "r"(addr));
}
__device__ __forceinline__ void mma_bf16(float* c, const uint32_t* a, const uint32_t* b) {
    asm volatile(
        "mma.sync.aligned.m16n8k16.row.col.f32.bf16.bf16.f32 "
        "{%0,%1,%2,%3}, {%4,%5,%6,%7}, {%8,%9}, {%0,%1,%2,%3};"
        : "+f"(c[0]), "+f"(c[1]), "+f"(c[2]), "+f"(c[3])
        : "r"(a[0]), "r"(a[1]), "r"(a[2]), "r"(a[3]), "r"(b[0]), "r"(b[1]));
}
__device__ __forceinline__ void cpa16(uint32_t dst, const void* src) {
    asm volatile("cp.async.ca.shared.global [%0], [%1], 16;" :: "r"(dst), "l"(src));
}
__device__ __forceinline__ void cpa_commit() {
    asm volatile("cp.async.commit_group;" ::: "memory");
}
__device__ __forceinline__ void cpa_wait1() {
    asm volatile("cp.async.wait_group 1;" ::: "memory");
}
__device__ __forceinline__ void sts64(uint32_t addr, uint32_t a, uint32_t b) {
    asm volatile("st.shared.v2.b32 [%0], {%1, %2};"
                 :: "r"(addr), "r"(a), "r"(b) : "memory");
}
// Pack 2 floats -> bf16x2 (x in low half, y in high half), and hi/lo split.
__device__ __forceinline__ uint32_t cvt_bf16x2(float hi_y, float lo_x) {
    uint32_t r;
    asm("cvt.rn.bf16x2.f32 %0, %1, %2;" : "=r"(r) : "f"(hi_y), "f"(lo_x));
    return r;
}
__device__ __forceinline__ void split2(float x, float y, uint32_t& h2, uint32_t& l2) {
    h2 = cvt_bf16x2(y, x);
    float fx = __uint_as_float(h2 << 16);
    float fy = __uint_as_float(h2 & 0xFFFF0000u);
    l2 = cvt_bf16x2(y - fy, x - fx);
}

// ---------------------------------------------------------------------------
// Weight pre-split: two fp32 matrices -> bf16 hi/lo each (one launch for two)
// ---------------------------------------------------------------------------
__global__ __launch_bounds__(256) void split_w2(
    const float* __restrict__ W0, __nv_bfloat16* __restrict__ Wh0,
    __nv_bfloat16* __restrict__ Wl0,
    const float* __restrict__ W1, __nv_bfloat16* __restrict__ Wh1,
    __nv_bfloat16* __restrict__ Wl1)
{
    int half = blockIdx.x >> 10;
    int i = ((blockIdx.x & 1023) * 256 + threadIdx.x) * 4;
    const float* W = half ? W1 : W0;
    __nv_bfloat16* Wh = half ? Wh1 : Wh0;
    __nv_bfloat16* Wl = half ? Wl1 : Wl0;
    float4 v = *reinterpret_cast<const float4*>(W + i);
    uint32_t h0, l0, h1, l1;
    split2(v.x, v.y, h0, l0);
    split2(v.z, v.w, h1, l1);
    uint32_t* whp = reinterpret_cast<uint32_t*>(Wh + i);
    uint32_t* wlp = reinterpret_cast<uint32_t*>(Wl + i);
    whp[0] = h0; whp[1] = h1;
    wlp[0] = l0; wlp[1] = l1;
}

// ---------------------------------------------------------------------------
// HMMA GEMM: C[M,1024] = A[M,1024] @ W[1024,1024]^T   (byte-identical to R9)
// ---------------------------------------------------------------------------
#define SUBT    8192
#define A_RING  (2 * 2 * SUBT)
#define W_BASE  A_RING
#define SMEMSZ  (A_RING + 3 * 2 * SUBT)   // 81920

template <int APRE>
__global__ __launch_bounds__(256, 2) void gemm_tc(
    const float* __restrict__ A32,
    const __nv_bfloat16* __restrict__ Ahp,
    const __nv_bfloat16* __restrict__ Alp,
    const __nv_bfloat16* __restrict__ Wh,
    const __nv_bfloat16* __restrict__ Wl,
    float* __restrict__ C, int act)
{
    extern __shared__ __align__(128) char smc[];
    const uint32_t sb0 = smem_u32(smc);
    const int tid = threadIdx.x;
    const int lane = tid & 31, w = tid >> 5;
    const int wm = w >> 2, wn = w & 3;
    const int bx = blockIdx.x, by = blockIdx.y;

    const float* Ab = A32 + (size_t)by * 128 * 1024;
    const __nv_bfloat16* AhB = Ahp + (size_t)by * 128 * 1024;
    const __nv_bfloat16* AlB = Alp + (size_t)by * 128 * 1024;
    const __nv_bfloat16* WhB = Wh + (size_t)bx * 128 * 1024;
    const __nv_bfloat16* WlB = Wl + (size_t)bx * 128 * 1024;

    float acc[4][4][4];
#pragma unroll
    for (int i = 0; i < 4; i++)
#pragma unroll
        for (int j = 0; j < 4; j++)
#pragma unroll
            for (int q = 0; q < 4; q++) acc[i][j][q] = 0.f;

    uint32_t fa[4][4], fbH[4][2], fbL[4][2];
    float4 areg[4];

    auto Ast = [&](int c) { return sb0 + (uint32_t)(c & 1) * (2 * SUBT); };
    auto Wst = [&](int c) { return sb0 + W_BASE + (uint32_t)(c % 3) * (2 * SUBT); };

    const int aRowBase = wm * 64 + (lane & 15);
    const int aHalf    = lane >> 4;
    const int swA      = (aRowBase >> 1) & 3;
    const uint32_t aByte = (uint32_t)aRowBase * 64;

    const int bRowBase = wn * 32 + ((lane >> 4) << 3) + (lane & 7);
    const int bHalf    = (lane >> 3) & 1;
    const int swB      = (bRowBase >> 1) & 3;
    const uint32_t bByte = (uint32_t)bRowBase * 64;

    auto LdgA = [&](int k0) {
#pragma unroll
        for (int i = 0; i < 4; i++) {
            int idx = tid + i * 256;
            int r = idx >> 3, c4 = idx & 7;
            areg[i] = *reinterpret_cast<const float4*>(
                Ab + (size_t)r * 1024 + k0 + c4 * 4);
        }
    };
    auto StsA = [&](uint32_t sb) {
#pragma unroll
        for (int i = 0; i < 4; i++) {
            int idx = tid + i * 256;
            int r = idx >> 3, c4 = idx & 7;
            int ch = c4 >> 1, sub = c4 & 1;
            uint32_t off = (uint32_t)(r * 64 + ((ch ^ ((r >> 1) & 3)) << 4) + sub * 8);
            float4 v = areg[i];
            uint32_t h0, l0, h1, l1;
            split2(v.x, v.y, h0, l0);
            split2(v.z, v.w, h1, l1);
            sts64(sb + off, h0, h1);
            sts64(sb + SUBT + off, l0, l1);
        }
    };
    auto CpA = [&](uint32_t sb, int k0) {
#pragma unroll
        for (int i = 0; i < 2; i++) {
            int idx = tid + i * 256;
            int r = idx >> 2, ch = idx & 3;
            uint32_t dst = (uint32_t)(r * 64 + ((ch ^ ((r >> 1) & 3)) << 4));
            size_t src = (size_t)r * 1024 + k0 + ch * 8;
            cpa16(sb + dst, AhB + src);
            cpa16(sb + SUBT + dst, AlB + src);
        }
    };
    auto CpW = [&](uint32_t sb, int k0) {
#pragma unroll
        for (int i = 0; i < 2; i++) {
            int idx = tid + i * 256;
            int r = idx >> 2, ch = idx & 3;
            uint32_t dst = (uint32_t)(r * 64 + ((ch ^ ((r >> 1) & 3)) << 4));
            size_t src = (size_t)r * 1024 + k0 + ch * 8;
            cpa16(sb + dst, WhB + src);
            cpa16(sb + SUBT + dst, WlB + src);
        }
    };

    auto LdA = [&](uint32_t base) {
#pragma unroll
        for (int mt = 0; mt < 4; mt++)
            ldsm_x4(fa[mt][0], fa[mt][1], fa[mt][2], fa[mt][3],
                    base + (uint32_t)mt * 1024);
    };
    auto LdB = [&](uint32_t b[4][2], uint32_t base) {
        ldsm_x4(b[0][0], b[0][1], b[1][0], b[1][1], base);
        ldsm_x4(b[2][0], b[2][1], b[3][0], b[3][1], base + 1024);
    };
    auto MmaAll = [&](uint32_t b[4][2]) {
#pragma unroll
        for (int mt = 0; mt < 4; mt++)
#pragma unroll
            for (int nf = 0; nf < 4; nf++)
                mma_bf16(acc[mt][nf], fa[mt], b[nf]);
    };

    if (APRE) {
        CpA(Ast(0), 0);
        CpW(Wst(0), 0);
        cpa_commit();
        CpW(Wst(1), 32);
        cpa_commit();
    } else {
        LdgA(0);
        StsA(Ast(0));
        CpW(Wst(0), 0);
        cpa_commit();
        CpW(Wst(1), 32);
        cpa_commit();
        LdgA(32);
    }

    for (int c = 0; c < 32; c++) {
        const uint32_t sa = Ast(c);
        const uint32_t sw = Wst(c);
        cpa_wait1();
        __syncthreads();

#pragma unroll
        for (int ks = 0; ks < 2; ks++) {
            const uint32_t ca = (uint32_t)(((2 * ks + aHalf) ^ swA) << 4);
            const uint32_t cb = (uint32_t)(((2 * ks + bHalf) ^ swB) << 4);
            LdA(sa + aByte + ca);
            LdB(fbH, sw + bByte + cb);
            MmaAll(fbH);
            LdB(fbL, sw + SUBT + bByte + cb);
            MmaAll(fbL);
            LdA(sa + SUBT + aByte + ca);
            MmaAll(fbH);
        }

        if (APRE) {
            if (c + 1 < 32) CpA(Ast(c + 1), (c + 1) * 32);
            cpa_commit();
            if (c + 2 < 32) CpW(Wst(c + 2), (c + 2) * 32);
            cpa_commit();
        } else {
            if (c + 1 < 32) StsA(Ast(c + 1));
            if (c + 2 < 32) CpW(Wst(c + 2), (c + 2) * 32);
            cpa_commit();
            cpa_commit();
            if (c + 2 < 32) LdgA((c + 2) * 32);
        }
    }

    const int mBase = by * 128 + wm * 64 + (lane >> 2);
    const int nBase = bx * 128 + wn * 32 + (lane & 3) * 2;
#pragma unroll
    for (int mt = 0; mt < 4; mt++) {
#pragma unroll
        for (int nf = 0; nf < 4; nf++) {
            int m = mBase + mt * 16;
            int n = nBase + nf * 8;
            float2 v0 = make_float2(acc[mt][nf][0], acc[mt][nf][1]);
            float2 v1 = make_float2(acc[mt][nf][2], acc[mt][nf][3]);
            if (act) {
                v0.x = fmaxf(v0.x, 0.f) + EPSF; v0.y = fmaxf(v0.y, 0.f) + EPSF;
                v1.x = fmaxf(v1.x, 0.f) + EPSF; v1.y = fmaxf(v1.y, 0.f) + EPSF;
            }
            *reinterpret_cast<float2*>(C + (size_t)m * 1024 + n) = v0;
            *reinterpret_cast<float2*>(C + (size_t)(m + 8) * 1024 + n) = v1;
        }
    }
}

// ---------------------------------------------------------------------------
// Zero kv / ktot
// ---------------------------------------------------------------------------
__global__ void zero_kv()
{
    int i = blockIdx.x * blockDim.x + threadIdx.x;
    if (i < B_ * H_ * DK_ * DK_) g_kv[i] = 0.f;
    if (i < B_ * H_) g_ktot[i] = 0.f;
}

// ---------------------------------------------------------------------------
// kv_reduce: 8x8 register tiles, float4 staging, 4-way s-split + smem merge
// ---------------------------------------------------------------------------
#define SCHUNK 512
#define KSTG   32

__global__ __launch_bounds__(256) void kv_reduce(
    const float* __restrict__ Kb, const float* __restrict__ Vb)
{
    __shared__ float sK[KSTG][DK_];
    __shared__ float sV[KSTG][DK_];
    __shared__ float sred[DK_ * DK_];

    const int bh = blockIdx.x;
    const int b = bh >> 4, h = bh & 15;
    const int s0 = blockIdx.y * SCHUNK;
    const int tid = threadIdx.x;
    const int g  = tid >> 6;
    const int t6 = tid & 63;
    const int d0 = (t6 >> 3) << 3;
    const int e0 = (t6 & 7) << 3;

    float acc[8][8];
#pragma unroll
    for (int i = 0; i < 8; i++)
#pragma unroll
        for (int j = 0; j < 8; j++) acc[i][j] = 0.f;

    float ksum = 0.f;
    const size_t base = ((size_t)b * S_ + s0) * D_ + h * DK_;

    for (int so = 0; so < SCHUNK; so += KSTG) {
#pragma unroll
        for (int i = 0; i < 2; i++) {
            int f = tid + i * 256;
            int r = f >> 4, c4 = (f & 15) << 2;
            size_t off = base + (size_t)(so + r) * D_ + c4;
            float4 k4 = *reinterpret_cast<const float4*>(Kb + off);
            float4 v4 = *reinterpret_cast<const float4*>(Vb + off);
            ksum += k4.x + k4.y + k4.z + k4.w;
            *reinterpret_cast<float4*>(&sK[r][c4]) = k4;
            *reinterpret_cast<float4*>(&sV[r][c4]) = v4;
        }
        __syncthreads();
#pragma unroll
        for (int sr = 0; sr < 8; sr++) {
            int s = g * 8 + sr;
            float kd[8], ve[8];
            *reinterpret_cast<float4*>(&kd[0]) =
                *reinterpret_cast<float4*>(&sK[s][d0]);
            *reinterpret_cast<float4*>(&kd[4]) =
                *reinterpret_cast<float4*>(&sK[s][d0 + 4]);
            *reinterpret_cast<float4*>(&ve[0]) =
                *reinterpret_cast<float4*>(&sV[s][e0]);
            *reinterpret_cast<float4*>(&ve[4]) =
                *reinterpret_cast<float4*>(&sV[s][e0 + 4]);
#pragma unroll
            for (int i = 0; i < 8; i++)
#pragma unroll
                for (int j = 0; j < 8; j++)
                    acc[i][j] = fmaf(kd[i], ve[j], acc[i][j]);
        }
        __syncthreads();
    }

    if (g == 0) {
#pragma unroll
        for (int i = 0; i < 8; i++)
#pragma unroll
            for (int j = 0; j < 8; j++)
                sred[(d0 + i) * DK_ + e0 + j] = acc[i][j];
    }
    __syncthreads();
#pragma unroll
    for (int gg = 1; gg < 4; gg++) {
        if (g == gg) {
#pragma unroll
            for (int i = 0; i < 8; i++)
#pragma unroll
                for (int j = 0; j < 8; j++)
                    sred[(d0 + i) * DK_ + e0 + j] += acc[i][j];
        }
        __syncthreads();
    }

    float* kvp = g_kv + (size_t)bh * DK_ * DK_;
    for (int t = tid; t < DK_ * DK_; t += 256)
        atomicAdd(&kvp[t], sred[t]);

#pragma unroll
    for (int o = 16; o > 0; o >>= 1)
        ksum += __shfl_xor_sync(0xFFFFFFFFu, ksum, o);
    if ((tid & 31) == 0) atomicAdd(&g_ktot[bh], ksum);
}

// ---------------------------------------------------------------------------
// apply_kv: 256 rows per CTA, transposed Q staging, 8x8 register tiles,
// zero mainloop barriers. No minBlocks bound (avoid forced reg spill).
// ---------------------------------------------------------------------------
#define QPAD 257
#define APPLY_SMEM ((DK_ * DK_ + DK_ * QPAD) * 4)   // 82176

__global__ __launch_bounds__(256) void apply_kv(
    const float* __restrict__ Qb,
    __nv_bfloat16* __restrict__ Ph, __nv_bfloat16* __restrict__ Pl)
{
    extern __shared__ float sdyn[];
    float* skv = sdyn;                  // [64*64]
    float* sQt = sdyn + DK_ * DK_;      // [64][QPAD] transposed Q

    const int bh = blockIdx.x;
    const int b = bh >> 4, h = bh & 15;
    const int tid = threadIdx.x;
    const int ri = tid >> 3;            // 0..31 -> rows 8ri..8ri+7
    const int cj = tid & 7;             // cols 8cj..8cj+7

    for (int t = tid; t < DK_ * DK_ / 4; t += 256)
        *reinterpret_cast<float4*>(&skv[t * 4]) =
            *reinterpret_cast<const float4*>(&g_kv[(size_t)bh * DK_ * DK_ + t * 4]);

    const float ktv = g_ktot[bh];
    const int row0 = blockIdx.y * 256;
    const size_t gbase = ((size_t)b * S_ + row0) * D_ + h * DK_;

#pragma unroll
    for (int i = 0; i < 16; i++) {
        int f = tid + i * 256;
        int r = f >> 4, c4 = (f & 15) << 2;
        float4 q4 = *reinterpret_cast<const float4*>(Qb + gbase + (size_t)r * D_ + c4);
        sQt[(c4 + 0) * QPAD + r] = q4.x;
        sQt[(c4 + 1) * QPAD + r] = q4.y;
        sQt[(c4 + 2) * QPAD + r] = q4.z;
        sQt[(c4 + 3) * QPAD + r] = q4.w;
    }
    __syncthreads();

    float acc[8][8];
    float qsum[8];
#pragma unroll
    for (int r = 0; r < 8; r++) {
        qsum[r] = 0.f;
#pragma unroll
        for (int c = 0; c < 8; c++) acc[r][c] = 0.f;
    }

#pragma unroll 4
    for (int d = 0; d < DK_; d++) {
        float qv[8], kvv[8];
#pragma unroll
        for (int r = 0; r < 8; r++) qv[r] = sQt[d * QPAD + ri * 8 + r];
        *reinterpret_cast<float4*>(&kvv[0]) =
            *reinterpret_cast<float4*>(&skv[d * DK_ + cj * 8]);
        *reinterpret_cast<float4*>(&kvv[4]) =
            *reinterpret_cast<float4*>(&skv[d * DK_ + cj * 8 + 4]);
#pragma unroll
        for (int r = 0; r < 8; r++) {
            qsum[r] += qv[r];
#pragma unroll
            for (int c = 0; c < 8; c++)
                acc[r][c] = fmaf(qv[r], kvv[c], acc[r][c]);
        }
    }

#pragma unroll
    for (int r = 0; r < 8; r++) {
        int row = ri * 8 + r;
        float nrm = 1.f / (qsum[r] * ktv + EPSF);
        size_t off = gbase + (size_t)row * D_ + cj * 8;
        uint32_t hv[4], lv[4];
#pragma unroll
        for (int c = 0; c < 4; c++)
            split2(acc[r][2 * c] * nrm, acc[r][2 * c + 1] * nrm, hv[c], lv[c]);
        *reinterpret_cast<float4*>(Ph + off) = make_float4(
            __uint_as_float(hv[0]), __uint_as_float(hv[1]),
            __uint_as_float(hv[2]), __uint_as_float(hv[3]));
        *reinterpret_cast<float4*>(Pl + off) = make_float4(
            __uint_as_float(lv[0]), __uint_as_float(lv[1]),
            __uint_as_float(lv[2]), __uint_as_float(lv[3]));
    }
}

// ---------------------------------------------------------------------------
// Launch
// ---------------------------------------------------------------------------
extern "C" void kernel_launch(void* const* d_in, const int* in_sizes, int n_in,
                              void* d_out, int out_size)
{
    const float* q  = (const float*)d_in[0];
    const float* k  = (const float*)d_in[1];
    const float* v  = (const float*)d_in[2];
    const float* Wq = (const float*)d_in[3];
    const float* Wk = (const float*)d_in[4];
    const float* Wv = (const float*)d_in[5];
    const float* Wo = (const float*)d_in[6];
    float* out = (float*)d_out;

    float *Qb, *Kb, *Vb;
    __nv_bfloat16 *whp, *wlp, *php, *plp;
    cudaGetSymbolAddress((void**)&Qb, g_Q);
    cudaGetSymbolAddress((void**)&Kb, g_K);
    cudaGetSymbolAddress((void**)&Vb, g_V);
    cudaGetSymbolAddress((void**)&whp, g_Wh);
    cudaGetSymbolAddress((void**)&wlp, g_Wl);
    cudaGetSymbolAddress((void**)&php, g_Ph);
    cudaGetSymbolAddress((void**)&plp, g_Pl);

    cudaFuncSetAttribute(gemm_tc<0>, cudaFuncAttributeMaxDynamicSharedMemorySize,
                         SMEMSZ);
    cudaFuncSetAttribute(gemm_tc<1>, cudaFuncAttributeMaxDynamicSharedMemorySize,
                         SMEMSZ);
    cudaFuncSetAttribute(apply_kv, cudaFuncAttributeMaxDynamicSharedMemorySize,
                         APPLY_SMEM);

    const size_t WS = 1024ull * 1024ull;
    dim3 gg(8, MROWS / 128);   // x = N tiles (fast), y = M tiles

    zero_kv<<<(B_ * H_ * DK_ * DK_ + 255) / 256, 256>>>();
    split_w2<<<2048, 256>>>(Wq, whp + 0 * WS, wlp + 0 * WS,
                            Wk, whp + 1 * WS, wlp + 1 * WS);
    split_w2<<<2048, 256>>>(Wv, whp + 2 * WS, wlp + 2 * WS,
                            Wo, whp + 3 * WS, wlp + 3 * WS);

    gemm_tc<0><<<gg, 256, SMEMSZ>>>(q, php, plp, whp + 0 * WS, wlp + 0 * WS, Qb, 1);
    gemm_tc<0><<<gg, 256, SMEMSZ>>>(k, php, plp, whp + 1 * WS, wlp + 1 * WS, Kb, 1);
    gemm_tc<0><<<gg, 256, SMEMSZ>>>(v, php, plp, whp + 2 * WS, wlp + 2 * WS, Vb, 0);

    kv_reduce<<<dim3(B_ * H_, S_ / SCHUNK), 256>>>(Kb, Vb);
    apply_kv<<<dim3(B_ * H_, S_ / 256), 256, APPLY_SMEM>>>(Qb, php, plp);

    gemm_tc<1><<<gg, 256, SMEMSZ>>>(nullptr, php, plp, whp + 3 * WS, wlp + 3 * WS,
                                    out, 0);
}

// round 12
// speedup vs baseline: 1.5396x; 1.0006x over previous
#include <cuda_runtime.h>
#include <cuda_bf16.h>
#include <cstdint>

// Problem constants
#define B_  4
#define S_  8192
#define D_  1024
#define H_  16
#define DK_ 64
#define EPSF 1e-6f
#define MROWS (B_ * S_)

// ---------------------------------------------------------------------------
// Scratch (device globals — no runtime allocation allowed)
// ---------------------------------------------------------------------------
__device__ float g_Q[(size_t)B_ * S_ * D_];
__device__ float g_K[(size_t)B_ * S_ * D_];
__device__ float g_V[(size_t)B_ * S_ * D_];
__device__ float g_kv[(size_t)B_ * H_ * DK_ * DK_];
__device__ float g_ktot[B_ * H_];
__device__ __nv_bfloat16 g_Wh[4ull * 1024 * 1024];
__device__ __nv_bfloat16 g_Wl[4ull * 1024 * 1024];
__device__ __nv_bfloat16 g_Ph[(size_t)MROWS * 1024];
__device__ __nv_bfloat16 g_Pl[(size_t)MROWS * 1024];

// ---------------------------------------------------------------------------
// PTX helpers (sm_80-level PTX only — ptxas target is sm_103 non-'a')
// ---------------------------------------------------------------------------
__device__ __forceinline__ uint32_t smem_u32(const void* p) {
    uint32_t a;
    asm("{ .reg .u64 t; cvta.to.shared.u64 t, %1; cvt.u32.u64 %0, t; }"
        : "=r"(a) : "l"(p));
    return a;
}
__device__ __forceinline__ void ldsm_x4(uint32_t& r0, uint32_t& r1,
                                        uint32_t& r2, uint32_t& r3, uint32_t addr) {
    asm volatile("ldmatrix.sync.aligned.m8n8.x4.shared.b16 {%0,%1,%2,%3}, [%4];"
                 : "=r"(r0), "=r"(r1), "=r"(r2), "=r"(r3) : "r"(addr));
}
__device__ __forceinline__ void mma_bf16(float* c, const uint32_t* a, const uint32_t* b) {
    asm volatile(
        "mma.sync.aligned.m16n8k16.row.col.f32.bf16.bf16.f32 "
        "{%0,%1,%2,%3}, {%4,%5,%6,%7}, {%8,%9}, {%0,%1,%2,%3};"
        : "+f"(c[0]), "+f"(c[1]), "+f"(c[2]), "+f"(c[3])
        : "r"(a[0]), "r"(a[1]), "r"(a[2]), "r"(a[3]), "r"(b[0]), "r"(b[1]));
}
__device__ __forceinline__ void cpa16(uint32_t dst, const void* src) {
    asm volatile("cp.async.ca.shared.global [%0], [%1], 16;" :: "r"(dst), "l"(src));
}
__device__ __forceinline__ void cpa_commit() {
    asm volatile("cp.async.commit_group;" ::: "memory");
}
__device__ __forceinline__ void cpa_wait1() {
    asm volatile("cp.async.wait_group 1;" ::: "memory");
}
__device__ __forceinline__ void sts64(uint32_t addr, uint32_t a, uint32_t b) {
    asm volatile("st.shared.v2.b32 [%0], {%1, %2};"
                 :: "r"(addr), "r"(a), "r"(b) : "memory");
}
// Pack 2 floats -> bf16x2 (x in low half, y in high half), and hi/lo split.
__device__ __forceinline__ uint32_t cvt_bf16x2(float hi_y, float lo_x) {
    uint32_t r;
    asm("cvt.rn.bf16x2.f32 %0, %1, %2;" : "=r"(r) : "f"(hi_y), "f"(lo_x));
    return r;
}
__device__ __forceinline__ void split2(float x, float y, uint32_t& h2, uint32_t& l2) {
    h2 = cvt_bf16x2(y, x);
    float fx = __uint_as_float(h2 << 16);
    float fy = __uint_as_float(h2 & 0xFFFF0000u);
    l2 = cvt_bf16x2(y - fy, x - fx);
}

// ---------------------------------------------------------------------------
// Weight pre-split: two fp32 matrices -> bf16 hi/lo each (one launch for two)
// ---------------------------------------------------------------------------
__global__ __launch_bounds__(256) void split_w2(
    const float* __restrict__ W0, __nv_bfloat16* __restrict__ Wh0,
    __nv_bfloat16* __restrict__ Wl0,
    const float* __restrict__ W1, __nv_bfloat16* __restrict__ Wh1,
    __nv_bfloat16* __restrict__ Wl1)
{
    int half = blockIdx.x >> 10;
    int i = ((blockIdx.x & 1023) * 256 + threadIdx.x) * 4;
    const float* W = half ? W1 : W0;
    __nv_bfloat16* Wh = half ? Wh1 : Wh0;
    __nv_bfloat16* Wl = half ? Wl1 : Wl0;
    float4 v = *reinterpret_cast<const float4*>(W + i);
    uint32_t h0, l0, h1, l1;
    split2(v.x, v.y, h0, l0);
    split2(v.z, v.w, h1, l1);
    uint32_t* whp = reinterpret_cast<uint32_t*>(Wh + i);
    uint32_t* wlp = reinterpret_cast<uint32_t*>(Wl + i);
    whp[0] = h0; whp[1] = h1;
    wlp[0] = l0; wlp[1] = l1;
}

// ---------------------------------------------------------------------------
// HMMA GEMM: C[M,1024] = A[M,1024] @ W[1024,1024]^T   (byte-identical to R9)
// ---------------------------------------------------------------------------
#define SUBT    8192
#define A_RING  (2 * 2 * SUBT)
#define W_BASE  A_RING
#define SMEMSZ  (A_RING + 3 * 2 * SUBT)   // 81920

template <int APRE>
__global__ __launch_bounds__(256, 2) void gemm_tc(
    const float* __restrict__ A32,
    const __nv_bfloat16* __restrict__ Ahp,
    const __nv_bfloat16* __restrict__ Alp,
    const __nv_bfloat16* __restrict__ Wh,
    const __nv_bfloat16* __restrict__ Wl,
    float* __restrict__ C, int act)
{
    extern __shared__ __align__(128) char smc[];
    const uint32_t sb0 = smem_u32(smc);
    const int tid = threadIdx.x;
    const int lane = tid & 31, w = tid >> 5;
    const int wm = w >> 2, wn = w & 3;
    const int bx = blockIdx.x, by = blockIdx.y;

    const float* Ab = A32 + (size_t)by * 128 * 1024;
    const __nv_bfloat16* AhB = Ahp + (size_t)by * 128 * 1024;
    const __nv_bfloat16* AlB = Alp + (size_t)by * 128 * 1024;
    const __nv_bfloat16* WhB = Wh + (size_t)bx * 128 * 1024;
    const __nv_bfloat16* WlB = Wl + (size_t)bx * 128 * 1024;

    float acc[4][4][4];
#pragma unroll
    for (int i = 0; i < 4; i++)
#pragma unroll
        for (int j = 0; j < 4; j++)
#pragma unroll
            for (int q = 0; q < 4; q++) acc[i][j][q] = 0.f;

    uint32_t fa[4][4], fbH[4][2], fbL[4][2];
    float4 areg[4];

    auto Ast = [&](int c) { return sb0 + (uint32_t)(c & 1) * (2 * SUBT); };
    auto Wst = [&](int c) { return sb0 + W_BASE + (uint32_t)(c % 3) * (2 * SUBT); };

    const int aRowBase = wm * 64 + (lane & 15);
    const int aHalf    = lane >> 4;
    const int swA      = (aRowBase >> 1) & 3;
    const uint32_t aByte = (uint32_t)aRowBase * 64;

    const int bRowBase = wn * 32 + ((lane >> 4) << 3) + (lane & 7);
    const int bHalf    = (lane >> 3) & 1;
    const int swB      = (bRowBase >> 1) & 3;
    const uint32_t bByte = (uint32_t)bRowBase * 64;

    auto LdgA = [&](int k0) {
#pragma unroll
        for (int i = 0; i < 4; i++) {
            int idx = tid + i * 256;
            int r = idx >> 3, c4 = idx & 7;
            areg[i] = *reinterpret_cast<const float4*>(
                Ab + (size_t)r * 1024 + k0 + c4 * 4);
        }
    };
    auto StsA = [&](uint32_t sb) {
#pragma unroll
        for (int i = 0; i < 4; i++) {
            int idx = tid + i * 256;
            int r = idx >> 3, c4 = idx & 7;
            int ch = c4 >> 1, sub = c4 & 1;
            uint32_t off = (uint32_t)(r * 64 + ((ch ^ ((r >> 1) & 3)) << 4) + sub * 8);
            float4 v = areg[i];
            uint32_t h0, l0, h1, l1;
            split2(v.x, v.y, h0, l0);
            split2(v.z, v.w, h1, l1);
            sts64(sb + off, h0, h1);
            sts64(sb + SUBT + off, l0, l1);
        }
    };
    auto CpA = [&](uint32_t sb, int k0) {
#pragma unroll
        for (int i = 0; i < 2; i++) {
            int idx = tid + i * 256;
            int r = idx >> 2, ch = idx & 3;
            uint32_t dst = (uint32_t)(r * 64 + ((ch ^ ((r >> 1) & 3)) << 4));
            size_t src = (size_t)r * 1024 + k0 + ch * 8;
            cpa16(sb + dst, AhB + src);
            cpa16(sb + SUBT + dst, AlB + src);
        }
    };
    auto CpW = [&](uint32_t sb, int k0) {
#pragma unroll
        for (int i = 0; i < 2; i++) {
            int idx = tid + i * 256;
            int r = idx >> 2, ch = idx & 3;
            uint32_t dst = (uint32_t)(r * 64 + ((ch ^ ((r >> 1) & 3)) << 4));
            size_t src = (size_t)r * 1024 + k0 + ch * 8;
            cpa16(sb + dst, WhB + src);
            cpa16(sb + SUBT + dst, WlB + src);
        }
    };

    auto LdA = [&](uint32_t base) {
#pragma unroll
        for (int mt = 0; mt < 4; mt++)
            ldsm_x4(fa[mt][0], fa[mt][1], fa[mt][2], fa[mt][3],
                    base + (uint32_t)mt * 1024);
    };
    auto LdB = [&](uint32_t b[4][2], uint32_t base) {
        ldsm_x4(b[0][0], b[0][1], b[1][0], b[1][1], base);
        ldsm_x4(b[2][0], b[2][1], b[3][0], b[3][1], base + 1024);
    };
    auto MmaAll = [&](uint32_t b[4][2]) {
#pragma unroll
        for (int mt = 0; mt < 4; mt++)
#pragma unroll
            for (int nf = 0; nf < 4; nf++)
                mma_bf16(acc[mt][nf], fa[mt], b[nf]);
    };

    if (APRE) {
        CpA(Ast(0), 0);
        CpW(Wst(0), 0);
        cpa_commit();
        CpW(Wst(1), 32);
        cpa_commit();
    } else {
        LdgA(0);
        StsA(Ast(0));
        CpW(Wst(0), 0);
        cpa_commit();
        CpW(Wst(1), 32);
        cpa_commit();
        LdgA(32);
    }

    for (int c = 0; c < 32; c++) {
        const uint32_t sa = Ast(c);
        const uint32_t sw = Wst(c);
        cpa_wait1();
        __syncthreads();

#pragma unroll
        for (int ks = 0; ks < 2; ks++) {
            const uint32_t ca = (uint32_t)(((2 * ks + aHalf) ^ swA) << 4);
            const uint32_t cb = (uint32_t)(((2 * ks + bHalf) ^ swB) << 4);
            LdA(sa + aByte + ca);
            LdB(fbH, sw + bByte + cb);
            MmaAll(fbH);
            LdB(fbL, sw + SUBT + bByte + cb);
            MmaAll(fbL);
            LdA(sa + SUBT + aByte + ca);
            MmaAll(fbH);
        }

        if (APRE) {
            if (c + 1 < 32) CpA(Ast(c + 1), (c + 1) * 32);
            cpa_commit();
            if (c + 2 < 32) CpW(Wst(c + 2), (c + 2) * 32);
            cpa_commit();
        } else {
            if (c + 1 < 32) StsA(Ast(c + 1));
            if (c + 2 < 32) CpW(Wst(c + 2), (c + 2) * 32);
            cpa_commit();
            cpa_commit();
            if (c + 2 < 32) LdgA((c + 2) * 32);
        }
    }

    const int mBase = by * 128 + wm * 64 + (lane >> 2);
    const int nBase = bx * 128 + wn * 32 + (lane & 3) * 2;
#pragma unroll
    for (int mt = 0; mt < 4; mt++) {
#pragma unroll
        for (int nf = 0; nf < 4; nf++) {
            int m = mBase + mt * 16;
            int n = nBase + nf * 8;
            float2 v0 = make_float2(acc[mt][nf][0], acc[mt][nf][1]);
            float2 v1 = make_float2(acc[mt][nf][2], acc[mt][nf][3]);
            if (act) {
                v0.x = fmaxf(v0.x, 0.f) + EPSF; v0.y = fmaxf(v0.y, 0.f) + EPSF;
                v1.x = fmaxf(v1.x, 0.f) + EPSF; v1.y = fmaxf(v1.y, 0.f) + EPSF;
            }
            *reinterpret_cast<float2*>(C + (size_t)m * 1024 + n) = v0;
            *reinterpret_cast<float2*>(C + (size_t)(m + 8) * 1024 + n) = v1;
        }
    }
}

// ---------------------------------------------------------------------------
// Zero kv / ktot
// ---------------------------------------------------------------------------
__global__ void zero_kv()
{
    int i = blockIdx.x * blockDim.x + threadIdx.x;
    if (i < B_ * H_ * DK_ * DK_) g_kv[i] = 0.f;
    if (i < B_ * H_) g_ktot[i] = 0.f;
}

// ---------------------------------------------------------------------------
// kv_reduce: 8x8 register tiles, float4 staging, 4-way s-split + smem merge
// ---------------------------------------------------------------------------
#define SCHUNK 512
#define KSTG   32

__global__ __launch_bounds__(256) void kv_reduce(
    const float* __restrict__ Kb, const float* __restrict__ Vb)
{
    __shared__ float sK[KSTG][DK_];
    __shared__ float sV[KSTG][DK_];
    __shared__ float sred[DK_ * DK_];

    const int bh = blockIdx.x;
    const int b = bh >> 4, h = bh & 15;
    const int s0 = blockIdx.y * SCHUNK;
    const int tid = threadIdx.x;
    const int g  = tid >> 6;
    const int t6 = tid & 63;
    const int d0 = (t6 >> 3) << 3;
    const int e0 = (t6 & 7) << 3;

    float acc[8][8];
#pragma unroll
    for (int i = 0; i < 8; i++)
#pragma unroll
        for (int j = 0; j < 8; j++) acc[i][j] = 0.f;

    float ksum = 0.f;
    const size_t base = ((size_t)b * S_ + s0) * D_ + h * DK_;

    for (int so = 0; so < SCHUNK; so += KSTG) {
#pragma unroll
        for (int i = 0; i < 2; i++) {
            int f = tid + i * 256;
            int r = f >> 4, c4 = (f & 15) << 2;
            size_t off = base + (size_t)(so + r) * D_ + c4;
            float4 k4 = *reinterpret_cast<const float4*>(Kb + off);
            float4 v4 = *reinterpret_cast<const float4*>(Vb + off);
            ksum += k4.x + k4.y + k4.z + k4.w;
            *reinterpret_cast<float4*>(&sK[r][c4]) = k4;
            *reinterpret_cast<float4*>(&sV[r][c4]) = v4;
        }
        __syncthreads();
#pragma unroll
        for (int sr = 0; sr < 8; sr++) {
            int s = g * 8 + sr;
            float kd[8], ve[8];
            *reinterpret_cast<float4*>(&kd[0]) =
                *reinterpret_cast<float4*>(&sK[s][d0]);
            *reinterpret_cast<float4*>(&kd[4]) =
                *reinterpret_cast<float4*>(&sK[s][d0 + 4]);
            *reinterpret_cast<float4*>(&ve[0]) =
                *reinterpret_cast<float4*>(&sV[s][e0]);
            *reinterpret_cast<float4*>(&ve[4]) =
                *reinterpret_cast<float4*>(&sV[s][e0 + 4]);
#pragma unroll
            for (int i = 0; i < 8; i++)
#pragma unroll
                for (int j = 0; j < 8; j++)
                    acc[i][j] = fmaf(kd[i], ve[j], acc[i][j]);
        }
        __syncthreads();
    }

    if (g == 0) {
#pragma unroll
        for (int i = 0; i < 8; i++)
#pragma unroll
            for (int j = 0; j < 8; j++)
                sred[(d0 + i) * DK_ + e0 + j] = acc[i][j];
    }
    __syncthreads();
#pragma unroll
    for (int gg = 1; gg < 4; gg++) {
        if (g == gg) {
#pragma unroll
            for (int i = 0; i < 8; i++)
#pragma unroll
                for (int j = 0; j < 8; j++)
                    sred[(d0 + i) * DK_ + e0 + j] += acc[i][j];
        }
        __syncthreads();
    }

    float* kvp = g_kv + (size_t)bh * DK_ * DK_;
    for (int t = tid; t < DK_ * DK_; t += 256)
        atomicAdd(&kvp[t], sred[t]);

#pragma unroll
    for (int o = 16; o > 0; o >>= 1)
        ksum += __shfl_xor_sync(0xFFFFFFFFu, ksum, o);
    if ((tid & 31) == 0) atomicAdd(&g_ktot[bh], ksum);
}

// ---------------------------------------------------------------------------
// apply_kv: 256 rows per CTA, transposed Q staging, 8x8 register tiles,
// zero mainloop barriers. No minBlocks bound (avoid forced reg spill).
// ---------------------------------------------------------------------------
#define QPAD 257
#define APPLY_SMEM ((DK_ * DK_ + DK_ * QPAD) * 4)   // 82176

__global__ __launch_bounds__(256) void apply_kv(
    const float* __restrict__ Qb,
    __nv_bfloat16* __restrict__ Ph, __nv_bfloat16* __restrict__ Pl)
{
    extern __shared__ float sdyn[];
    float* skv = sdyn;                  // [64*64]
    float* sQt = sdyn + DK_ * DK_;      // [64][QPAD] transposed Q

    const int bh = blockIdx.x;
    const int b = bh >> 4, h = bh & 15;
    const int tid = threadIdx.x;
    const int ri = tid >> 3;            // 0..31 -> rows 8ri..8ri+7
    const int cj = tid & 7;             // cols 8cj..8cj+7

    for (int t = tid; t < DK_ * DK_ / 4; t += 256)
        *reinterpret_cast<float4*>(&skv[t * 4]) =
            *reinterpret_cast<const float4*>(&g_kv[(size_t)bh * DK_ * DK_ + t * 4]);

    const float ktv = g_ktot[bh];
    const int row0 = blockIdx.y * 256;
    const size_t gbase = ((size_t)b * S_ + row0) * D_ + h * DK_;

#pragma unroll
    for (int i = 0; i < 16; i++) {
        int f = tid + i * 256;
        int r = f >> 4, c4 = (f & 15) << 2;
        float4 q4 = *reinterpret_cast<const float4*>(Qb + gbase + (size_t)r * D_ + c4);
        sQt[(c4 + 0) * QPAD + r] = q4.x;
        sQt[(c4 + 1) * QPAD + r] = q4.y;
        sQt[(c4 + 2) * QPAD + r] = q4.z;
        sQt[(c4 + 3) * QPAD + r] = q4.w;
    }
    __syncthreads();

    float acc[8][8];
    float qsum[8];
#pragma unroll
    for (int r = 0; r < 8; r++) {
        qsum[r] = 0.f;
#pragma unroll
        for (int c = 0; c < 8; c++) acc[r][c] = 0.f;
    }

#pragma unroll 4
    for (int d = 0; d < DK_; d++) {
        float qv[8], kvv[8];
#pragma unroll
        for (int r = 0; r < 8; r++) qv[r] = sQt[d * QPAD + ri * 8 + r];
        *reinterpret_cast<float4*>(&kvv[0]) =
            *reinterpret_cast<float4*>(&skv[d * DK_ + cj * 8]);
        *reinterpret_cast<float4*>(&kvv[4]) =
            *reinterpret_cast<float4*>(&skv[d * DK_ + cj * 8 + 4]);
#pragma unroll
        for (int r = 0; r < 8; r++) {
            qsum[r] += qv[r];
#pragma unroll
            for (int c = 0; c < 8; c++)
                acc[r][c] = fmaf(qv[r], kvv[c], acc[r][c]);
        }
    }

#pragma unroll
    for (int r = 0; r < 8; r++) {
        int row = ri * 8 + r;
        float nrm = 1.f / (qsum[r] * ktv + EPSF);
        size_t off = gbase + (size_t)row * D_ + cj * 8;
        uint32_t hv[4], lv[4];
#pragma unroll
        for (int c = 0; c < 4; c++)
            split2(acc[r][2 * c] * nrm, acc[r][2 * c + 1] * nrm, hv[c], lv[c]);
        *reinterpret_cast<float4*>(Ph + off) = make_float4(
            __uint_as_float(hv[0]), __uint_as_float(hv[1]),
            __uint_as_float(hv[2]), __uint_as_float(hv[3]));
        *reinterpret_cast<float4*>(Pl + off) = make_float4(
            __uint_as_float(lv[0]), __uint_as_float(lv[1]),
            __uint_as_float(lv[2]), __uint_as_float(lv[3]));
    }
}

// ---------------------------------------------------------------------------
// Launch
// ---------------------------------------------------------------------------
extern "C" void kernel_launch(void* const* d_in, const int* in_sizes, int n_in,
                              void* d_out, int out_size)
{
    const float* q  = (const float*)d_in[0];
    const float* k  = (const float*)d_in[1];
    const float* v  = (const float*)d_in[2];
    const float* Wq = (const float*)d_in[3];
    const float* Wk = (const float*)d_in[4];
    const float* Wv = (const float*)d_in[5];
    const float* Wo = (const float*)d_in[6];
    float* out = (float*)d_out;

    float *Qb, *Kb, *Vb;
    __nv_bfloat16 *whp, *wlp, *php, *plp;
    cudaGetSymbolAddress((void**)&Qb, g_Q);
    cudaGetSymbolAddress((void**)&Kb, g_K);
    cudaGetSymbolAddress((void**)&Vb, g_V);
    cudaGetSymbolAddress((void**)&whp, g_Wh);
    cudaGetSymbolAddress((void**)&wlp, g_Wl);
    cudaGetSymbolAddress((void**)&php, g_Ph);
    cudaGetSymbolAddress((void**)&plp, g_Pl);

    cudaFuncSetAttribute(gemm_tc<0>, cudaFuncAttributeMaxDynamicSharedMemorySize,
                         SMEMSZ);
    cudaFuncSetAttribute(gemm_tc<1>, cudaFuncAttributeMaxDynamicSharedMemorySize,
                         SMEMSZ);
    cudaFuncSetAttribute(apply_kv, cudaFuncAttributeMaxDynamicSharedMemorySize,
                         APPLY_SMEM);

    const size_t WS = 1024ull * 1024ull;
    dim3 gg(8, MROWS / 128);   // x = N tiles (fast), y = M tiles

    zero_kv<<<(B_ * H_ * DK_ * DK_ + 255) / 256, 256>>>();
    split_w2<<<2048, 256>>>(Wq, whp + 0 * WS, wlp + 0 * WS,
                            Wk, whp + 1 * WS, wlp + 1 * WS);
    split_w2<<<2048, 256>>>(Wv, whp + 2 * WS, wlp + 2 * WS,
                            Wo, whp + 3 * WS, wlp + 3 * WS);

    gemm_tc<0><<<gg, 256, SMEMSZ>>>(q, php, plp, whp + 0 * WS, wlp + 0 * WS, Qb, 1);
    gemm_tc<0><<<gg, 256, SMEMSZ>>>(k, php, plp, whp + 1 * WS, wlp + 1 * WS, Kb, 1);
    gemm_tc<0><<<gg, 256, SMEMSZ>>>(v, php, plp, whp + 2 * WS, wlp + 2 * WS, Vb, 0);

    kv_reduce<<<dim3(B_ * H_, S_ / SCHUNK), 256>>>(Kb, Vb);
    apply_kv<<<dim3(B_ * H_, S_ / 256), 256, APPLY_SMEM>>>(Qb, php, plp);

    gemm_tc<1><<<gg, 256, SMEMSZ>>>(nullptr, php, plp, whp + 3 * WS, wlp + 3 * WS,
                                    out, 0);
}